// round 13
// baseline (speedup 1.0000x reference)
#include <cuda_runtime.h>
#include <cstdint>

// FPN Pooler: multi-level ROIAlign, hybrid.
//  - direct role (R8 path): scattered 16x LDG.32 per bin; best for small windows.
//  - staged role: warp-autonomous cp.async(16B) window staging into smem +
//    16x LDS.32 per bin; best for big windows (removes L1 sector re-touch).
// One kernel, grid = 8N: bx<4N direct role, bx>=4N staged role; each block
// classifies its box identically and exits if the box belongs to the other role.
// feats NCHW f32: f0 [2,256,200,200], f1 [2,256,100,100], f2 [2,256,50,50], f3 [2,256,25,25]
// boxes [1000,4], img_ids [1000] -> out [1000,256,7,7] f32

#define P 14           // OUT*SR samples per axis
#define BLOCK 256      // 8 warps
#define ACT 196        // direct role: 4*49 active threads
#define QCH 64         // channels per block (quarter)
#define ITERS 16       // direct role: QCH/4 channels per thread
#define TILE 1344      // floats per warp tile (max needed ~1240 given nr<=31)
#define SMIN 192       // staged when window elems >= SMIN (and W>=100, nr<=31)

__global__ __launch_bounds__(BLOCK, 4) void pooler_kernel(
    const float* __restrict__ f0, const float* __restrict__ f1,
    const float* __restrict__ f2, const float* __restrict__ f3,
    const float* __restrict__ boxes, const int* __restrict__ img_ids,
    float* __restrict__ out)
{
    const int bx = blockIdx.x;
    const int Nq = gridDim.x >> 1;            // 4N
    const bool staged_role = bx >= Nq;
    const int sub = staged_role ? bx - Nq : bx;
    const int n   = sub >> 2;
    const int q   = sub & 3;                  // channel quarter
    const int tid = threadIdx.x;
    const int warp = tid >> 5, lane = tid & 31;

    __shared__ float s_tile[8][TILE];
    __shared__ int   s_x0[P], s_x1[P], s_y0[P], s_y1[P];      // raw feature coords
    __shared__ float s_ax0[P], s_ax1[P], s_ay0[P], s_ay1[P];  // folded weights
    __shared__ int   s_tx0[P], s_tx1[P], s_ty0[P], s_ty1[P];  // staged: tile-relative
    __shared__ const float* s_base;
    __shared__ int s_HW, s_W;

    // ---- per-box geometry phase 1 ----
    {
        const float bx1 = boxes[4*n+0], by1 = boxes[4*n+1];
        const float bx2 = boxes[4*n+2], by2 = boxes[4*n+3];
        const float sq  = sqrtf((bx2 - bx1) * (by2 - by1));
        float lf = floorf(4.0f + log2f(sq / 224.0f + 1e-6f));
        lf = fminf(fmaxf(lf, 2.0f), 5.0f);
        const int lvl = (int)lf - 2;

        int H, W; float scale; const float* fp;
        switch (lvl) {
            case 0:  H = 200; W = 200; scale = 0.25f;    fp = f0; break;
            case 1:  H = 100; W = 100; scale = 0.125f;   fp = f1; break;
            case 2:  H = 50;  W = 50;  scale = 0.0625f;  fp = f2; break;
            default: H = 25;  W = 25;  scale = 0.03125f; fp = f3; break;
        }
        const int HW = H * W;

        const float rx1 = bx1 * scale, ry1 = by1 * scale;
        const float roi_w = fmaxf(bx2 * scale - rx1, 1.0f);
        const float roi_h = fmaxf(by2 * scale - ry1, 1.0f);
        const float bw = roi_w * (1.0f / 7.0f);
        const float bh = roi_h * (1.0f / 7.0f);

        if (tid < P) {
            const int i = tid, p = i >> 1, r = i & 1;
            const float xg = rx1 + (float)p * bw + ((float)r + 0.5f) * bw * 0.5f;
            const float vx = (xg >= -1.0f && xg <= (float)W) ? 1.0f : 0.0f;
            float x = fminf(fmaxf(xg, 0.0f), (float)(W - 1));
            const int x0 = (int)x;
            s_x0[i] = x0;
            s_x1[i] = min(x0 + 1, W - 1);
            const float lx = x - (float)x0;
            s_ax0[i] = vx * (1.0f - lx);
            s_ax1[i] = vx * lx;
        } else if (tid >= 16 && tid < 16 + P) {
            const int i = tid - 16, p = i >> 1, r = i & 1;
            const float yg = ry1 + (float)p * bh + ((float)r + 0.5f) * bh * 0.5f;
            const float vy = (yg >= -1.0f && yg <= (float)H) ? 0.25f : 0.0f;  // fold mean
            float y = fminf(fmaxf(yg, 0.0f), (float)(H - 1));
            const int y0 = (int)y;
            s_y0[i] = y0;
            s_y1[i] = min(y0 + 1, H - 1);
            const float ly = y - (float)y0;
            s_ay0[i] = vy * (1.0f - ly);
            s_ay1[i] = vy * ly;
        } else if (tid == 32) {
            const int img = __ldg(img_ids + n);
            s_base = fp + (size_t)img * 256 * HW;
            s_HW   = HW;
            s_W    = W;
        }
    }
    __syncthreads();

    const int W  = s_W;
    const int HW = s_HW;
    const int clo = s_x0[0], rlo = s_y0[0];
    const int nc  = s_x1[P-1] - clo + 1;
    const int nr  = s_y1[P-1] - rlo + 1;

    // staged-path window parameters (identical in both roles -> exact partition)
    const int a0c    = clo & ~3;
    const int shift  = clo - a0c;
    const int cq4    = (shift + nc + 3) >> 2;     // 16B chunks per row
    const int stride = cq4 * 4 + 4;               // tile row stride (floats), mult of 4
    const bool big = (W >= 100) && (nr * nc >= SMIN) && (nr <= 31)
                   && (nr * stride <= TILE);

    if (!staged_role) {
        // ================= DIRECT ROLE (R8 path) =================
        if (big || tid >= ACT) return;

        const int csub = tid / 49;
        const int bin  = tid - csub * 49;
        const int ph = bin / 7, pw = bin - ph * 7;
        const int iyA = 2*ph, iyB = iyA + 1;
        const int ixA = 2*pw, ixB = ixA + 1;

        const int r0 = s_y0[iyA] * W, r1 = s_y1[iyA] * W;
        const int r2 = s_y0[iyB] * W, r3 = s_y1[iyB] * W;
        const int c0 = s_x0[ixA],  c1 = s_x1[ixA];
        const int c2 = s_x0[ixB],  c3 = s_x1[ixB];
        const float a0 = s_ay0[iyA], a1 = s_ay1[iyA];
        const float a2 = s_ay0[iyB], a3 = s_ay1[iyB];
        const float b0 = s_ax0[ixA], b1 = s_ax1[ixA];
        const float b2 = s_ax0[ixB], b3 = s_ax1[ixB];

        const int i00 = r0+c0, i01 = r0+c1, i02 = r0+c2, i03 = r0+c3;
        const int i10 = r1+c0, i11 = r1+c1, i12 = r1+c2, i13 = r1+c3;
        const int i20 = r2+c0, i21 = r2+c1, i22 = r2+c2, i23 = r2+c3;
        const int i30 = r3+c0, i31 = r3+c1, i32 = r3+c2, i33 = r3+c3;

        const size_t chStep = (size_t)4 * HW;
        const float* fc = s_base + (size_t)(q * QCH + csub) * HW;
        float* outp = out + (size_t)n * 12544 + (size_t)q * (QCH * 49) + tid;

        #pragma unroll 1
        for (int i = 0; i < ITERS; ++i) {
            const float p00 = __ldg(fc + i00), p01 = __ldg(fc + i01);
            const float p02 = __ldg(fc + i02), p03 = __ldg(fc + i03);
            const float p10 = __ldg(fc + i10), p11 = __ldg(fc + i11);
            const float p12 = __ldg(fc + i12), p13 = __ldg(fc + i13);
            const float p20 = __ldg(fc + i20), p21 = __ldg(fc + i21);
            const float p22 = __ldg(fc + i22), p23 = __ldg(fc + i23);
            const float p30 = __ldg(fc + i30), p31 = __ldg(fc + i31);
            const float p32 = __ldg(fc + i32), p33 = __ldg(fc + i33);

            float t0 = b0*p00 + b1*p01 + b2*p02 + b3*p03;
            float t1 = b0*p10 + b1*p11 + b2*p12 + b3*p13;
            float t2 = b0*p20 + b1*p21 + b2*p22 + b3*p23;
            float t3 = b0*p30 + b1*p31 + b2*p32 + b3*p33;

            *outp = a0*t0 + a1*t1 + a2*t2 + a3*t3;

            fc += chStep;
            outp += ACT;
        }
    } else {
        // ================= STAGED ROLE =================
        if (!big) return;

        // phase 2: tile-relative tables (distinct arrays, no race)
        if (tid < P) {
            s_tx0[tid] = s_x0[tid] - clo + shift;
            s_tx1[tid] = s_x1[tid] - clo + shift;
        } else if (tid >= 16 && tid < 16 + P) {
            const int i = tid - 16;
            s_ty0[i] = (s_y0[i] - rlo) * stride;
            s_ty1[i] = (s_y1[i] - rlo) * stride;
        }
        __syncthreads();

        // per-lane geometry for 2 bins (packed u16 indices)
        int rowp0[2], rowp1[2], colp0[2], colp1[2];
        float wa0[2], wa1[2], wa2[2], wa3[2];
        float wb0[2], wb1[2], wb2[2], wb3[2];
        #pragma unroll
        for (int s = 0; s < 2; ++s) {
            const int bin = min(lane + 32 * s, 48);
            const int ph = bin / 7, pw = bin - ph * 7;
            const int iyA = 2*ph, iyB = iyA + 1;
            const int ixA = 2*pw, ixB = ixA + 1;
            rowp0[s] = s_ty0[iyA] | (s_ty1[iyA] << 16);
            rowp1[s] = s_ty0[iyB] | (s_ty1[iyB] << 16);
            colp0[s] = s_tx0[ixA] | (s_tx1[ixA] << 16);
            colp1[s] = s_tx0[ixB] | (s_tx1[ixB] << 16);
            wa0[s] = s_ay0[iyA]; wa1[s] = s_ay1[iyA];
            wa2[s] = s_ay0[iyB]; wa3[s] = s_ay1[iyB];
            wb0[s] = s_ax0[ixA]; wb1[s] = s_ax1[ixA];
            wb2[s] = s_ax0[ixB]; wb3[s] = s_ax1[ixB];
        }

        float* tile = s_tile[warp];
        const uint32_t tbase = (uint32_t)__cvta_generic_to_shared(tile);

        // lane grouping for staging: pow2 chunks/row
        const int lg  = (cq4 > 16) ? 5 : (cq4 > 8) ? 4 : (cq4 > 4) ? 3 : 2;
        const int rpp = 32 >> lg;
        const int subc = lane & ((1 << lg) - 1);
        const int rof  = lane >> lg;
        const bool lact = subc < cq4;

        const float* gwin = s_base + (size_t)(q * QCH + warp * 8) * HW
                          + (size_t)rlo * W + a0c;
        float* outw = out + (size_t)n * 12544 + (size_t)(q * QCH + warp * 8) * 49;

        #pragma unroll 1
        for (int it = 0; it < 8; ++it) {
            const float* gp = gwin + (size_t)it * HW;

            // stage window: one cp.async(16B) per chunk, coalesced per row
            #pragma unroll 2
            for (int rb = 0; rb < nr; rb += rpp) {
                const int r = rb + rof;
                if (lact && r < nr) {
                    const float* ga = gp + r * W + subc * 4;
                    const uint32_t sa = tbase + (uint32_t)(r * stride + subc * 4) * 4u;
                    asm volatile("cp.async.cg.shared.global [%0], [%1], 16;\n"
                                 :: "r"(sa), "l"(ga));
                }
            }
            asm volatile("cp.async.commit_group;\n" ::: "memory");
            asm volatile("cp.async.wait_group 0;\n" ::: "memory");
            __syncwarp();

            // compute 2 bins per lane from tile
            #pragma unroll
            for (int s = 0; s < 2; ++s) {
                const int bin = lane + 32 * s;
                if (bin < 49) {
                    const int tA0 = rowp0[s] & 0xFFFF, tA1 = rowp0[s] >> 16;
                    const int tB0 = rowp1[s] & 0xFFFF, tB1 = rowp1[s] >> 16;
                    const int cA0 = colp0[s] & 0xFFFF, cA1 = colp0[s] >> 16;
                    const int cB0 = colp1[s] & 0xFFFF, cB1 = colp1[s] >> 16;

                    float t0 = wb0[s]*tile[tA0+cA0] + wb1[s]*tile[tA0+cA1]
                             + wb2[s]*tile[tA0+cB0] + wb3[s]*tile[tA0+cB1];
                    float t1 = wb0[s]*tile[tA1+cA0] + wb1[s]*tile[tA1+cA1]
                             + wb2[s]*tile[tA1+cB0] + wb3[s]*tile[tA1+cB1];
                    float t2 = wb0[s]*tile[tB0+cA0] + wb1[s]*tile[tB0+cA1]
                             + wb2[s]*tile[tB0+cB0] + wb3[s]*tile[tB0+cB1];
                    float t3 = wb0[s]*tile[tB1+cA0] + wb1[s]*tile[tB1+cA1]
                             + wb2[s]*tile[tB1+cB0] + wb3[s]*tile[tB1+cB1];

                    outw[it * 49 + bin] = wa0[s]*t0 + wa1[s]*t1 + wa2[s]*t2 + wa3[s]*t3;
                }
            }
            __syncwarp();   // reads done before next channel overwrites tile
        }
    }
}

extern "C" void kernel_launch(void* const* d_in, const int* in_sizes, int n_in,
                              void* d_out, int out_size)
{
    const float* f0    = (const float*)d_in[0];
    const float* f1    = (const float*)d_in[1];
    const float* f2    = (const float*)d_in[2];
    const float* f3    = (const float*)d_in[3];
    const float* boxes = (const float*)d_in[4];
    const int*   imgs  = (const int*)d_in[5];
    float* out = (float*)d_out;

    const int N = in_sizes[4] / 4;   // 1000 boxes
    pooler_kernel<<<N * 8, BLOCK>>>(f0, f1, f2, f3, boxes, imgs, out);
}